// round 14
// baseline (speedup 1.0000x reference)
#include <cuda_runtime.h>

// 2-layer LSTM (H=50), T=65536 serial steps, one persistent CTA, 256 threads.
// R12 skeleton (shuffle-quad gates, overlapping 8-warp unit coverage, 2
// barriers) with the Phase-B y-reduction tail removed: instead of a 3-deep
// shfl.xor butterfly (~78 cyc serial after h2v), the k==0 writer lane stores
// wout[u]*h2v into parr[u] (one STS); Phase A sums the 52-float parr with a
// packed add tree. Trades ~12 Phase-A issue slots for ~100 cyc of Phase-B
// critical path.

#define HDIM     50
#define INP      8
#define CHUNK    1024
#define NTHREADS 256

typedef unsigned long long u64;

__device__ __forceinline__ u64 pk2(float lo, float hi) {
    u64 r; asm("mov.b64 %0, {%1,%2};" : "=l"(r) : "f"(lo), "f"(hi)); return r;
}
__device__ __forceinline__ float2 upk2(u64 v) {
    float2 f; asm("mov.b64 {%0,%1}, %2;" : "=f"(f.x), "=f"(f.y) : "l"(v)); return f;
}
__device__ __forceinline__ u64 ffma2(u64 a, u64 b, u64 c) {
    u64 d; asm("fma.rn.f32x2 %0, %1, %2, %3;" : "=l"(d) : "l"(a), "l"(b), "l"(c)); return d;
}
__device__ __forceinline__ u64 add2(u64 a, u64 b) {
    u64 d; asm("add.rn.f32x2 %0, %1, %2;" : "=l"(d) : "l"(a), "l"(b)); return d;
}
__device__ __forceinline__ float tanha(float x) {
    float r; asm("tanh.approx.f32 %0, %1;" : "=f"(r) : "f"(x)); return r;
}

__global__ __launch_bounds__(NTHREADS, 1)
void lstm_r14_kernel(const float* __restrict__ input_seq,
                     const float* __restrict__ W_ih1, const float* __restrict__ W_hh1,
                     const float* __restrict__ b_ih1, const float* __restrict__ b_hh1,
                     const float* __restrict__ W_ih2, const float* __restrict__ W_hh2,
                     const float* __restrict__ b_ih2, const float* __restrict__ b_hh2,
                     const float* __restrict__ W_out, const float* __restrict__ b_out,
                     float* __restrict__ out, int T)
{
    __shared__ __align__(16) float sh1[52];    // h1(s), [50..51]=0
    __shared__ __align__(16) float sh2[52];    // h2(s), [50..51]=0
    __shared__ __align__(16) float parr[52];   // wout[u]*h2[u], [50..51]=0
    __shared__ __align__(16) float xbuf[(CHUNK + 1) * INP];

    const int t = threadIdx.x;
    const int w = t >> 5;
    const int l = t & 31;
    const int k = l >> 3;                 // gate kind: 0=i 1=f 2=g 3=o
    const int j0 = l & 7;                 // unit-within-warp
    const int u = 6 * w + j0;             // unit 0..49 (overlapping coverage)
    const bool writer = (j0 < 6) || (w == 7);   // unique owner of unit u
    const int row = k * HDIM + u;

    // activation: act(x) = fmaf(tanha(K*x), K, A); K folded into the weights
    const float actK = (k == 2) ? 1.0f : 0.5f;
    const float actA = (k == 2) ? 0.0f : 0.5f;

    // ---- per-thread full-row weights, pre-scaled by actK (f32x2; [25]=pad)
    u64 wx[3], wh1[26], wi2[26], wh2[26];
    float w6K, w7K, bb1K, bb2K;
    {
        const float* r1 = W_ih1 + row * INP;
        wx[0] = pk2(actK * r1[0], actK * r1[1]);
        wx[1] = pk2(actK * r1[2], actK * r1[3]);
        wx[2] = pk2(actK * r1[4], actK * r1[5]);
        w6K = actK * r1[6]; w7K = actK * r1[7];
        const float* r2 = W_hh1 + row * HDIM;
        const float* r3 = W_ih2 + row * HDIM;
        const float* r4 = W_hh2 + row * HDIM;
        #pragma unroll
        for (int j = 0; j < 25; ++j) {
            wh1[j] = pk2(actK * r2[2*j], actK * r2[2*j+1]);
            wi2[j] = pk2(actK * r3[2*j], actK * r3[2*j+1]);
            wh2[j] = pk2(actK * r4[2*j], actK * r4[2*j+1]);
        }
        wh1[25] = 0ULL; wi2[25] = 0ULL; wh2[25] = 0ULL;
        bb1K = actK * (b_ih1[row] + b_hh1[row]);
        bb2K = actK * (b_ih2[row] + b_hh2[row]);
    }
    const float bo = b_out[0];
    const float wout_u = W_out[u];
    if (t < 52) { sh1[t] = 0.0f; sh2[t] = 0.0f; parr[t] = 0.0f; }

    float c1 = 0.0f, c2 = 0.0f, err = 0.0f, a1p = 0.0f;
    float x7_use = 0.0f, x7_next = 0.0f;
    __syncthreads();

    #pragma unroll 1
    for (int s = 0; s < T; ++s) {
        const int lo = s & (CHUNK - 1);
        if (lo == 0) {
            // old xbuf fully consumed at BAR_B of step s-1
            const float4* src = (const float4*)(input_seq + (size_t)s * INP);
            float4* dst = (float4*)xbuf;
            int n4 = (CHUNK + 1) * 2;
            int rem4 = (T - s) * 2;
            if (rem4 < n4) n4 = rem4;
            for (int i = t; i < n4; i += NTHREADS) dst[i] = src[i];
            __syncthreads();
            if (s == 0) {
                // bootstrap a1p(0) = K*(bb1 + W_ih1 @ x(0)[0..6]); x7_next = x(0)[7]
                float4 xa = *(const float4*)(xbuf);
                float4 xb = *(const float4*)(xbuf + 4);
                u64 a0 = ffma2(wx[0], pk2(xa.x, xa.y), pk2(bb1K, 0.0f));
                u64 a1 = ffma2(wx[1], pk2(xa.z, xa.w), pk2(w6K * xb.z, 0.0f));
                a0 = ffma2(wx[2], pk2(xb.x, xb.y), a0);
                float2 f = upk2(add2(a0, a1));
                a1p = f.x + f.y;
                x7_next = xb.w;
            }
        }

        // ================= Phase A =================
        // x(s+1) early loads + W_ih1@x FMAs (off-path; carried into Phase B)
        const float* xn = &xbuf[(lo + 1) * INP];
        float4 xa = *(const float4*)(xn);
        float4 xb = *(const float4*)(xn + 4);
        u64 a0 = ffma2(wx[0], pk2(xa.x, xa.y), pk2(bb1K, 0.0f));
        u64 a1 = ffma2(wx[1], pk2(xa.z, xa.w), pk2(w6K * xb.z, 0.0f));
        a0 = ffma2(wx[2], pk2(xb.x, xb.y), a0);

        // y(s-1) = bo + sum(parr) via packed add tree
        {
            const float4* pv = (const float4*)parr;
            float4 p0 = pv[0], p1 = pv[1], p2 = pv[2];
            float4 p3 = pv[3], p4 = pv[4], p5 = pv[5];
            float4 p6 = pv[6], p7 = pv[7], p8 = pv[8];
            float4 p9 = pv[9], pa = pv[10], pb = pv[11];
            float4 pc = pv[12];
            float s0 = ((p0.x + p0.y) + (p0.z + p0.w)) + ((p1.x + p1.y) + (p1.z + p1.w));
            float s1 = ((p2.x + p2.y) + (p2.z + p2.w)) + ((p3.x + p3.y) + (p3.z + p3.w));
            float s2 = ((p4.x + p4.y) + (p4.z + p4.w)) + ((p5.x + p5.y) + (p5.z + p5.w));
            float s3 = ((p6.x + p6.y) + (p6.z + p6.w)) + ((p7.x + p7.y) + (p7.z + p7.w));
            float s4 = ((p8.x + p8.y) + (p8.z + p8.w)) + ((p9.x + p9.y) + (p9.z + p9.w));
            float s5 = ((pa.x + pa.y) + (pa.z + pa.w)) + ((pb.x + pb.y) + (pb.z + pb.w));
            float s6 = (pc.x + pc.y) + (pc.z + pc.w);
            float y = bo + (((s0 + s1) + (s2 + s3)) + ((s4 + s5) + s6));
            err = (s != 0) ? fmaf(0.1f, x7_use - y, 0.9f * err) : 0.0f;
            if (t == 0 && s != 0) out[s - 1] = y;
        }

        // W_hh2 @ h2(s-1), 4 ILP chains (carried across BAR_A)
        u64 q0 = pk2(bb2K, 0.0f), q1 = pk2(0.0f, 0.0f), q2 = q1, q3 = q1;
        {
            const float4* hv = (const float4*)sh2;
            #pragma unroll
            for (int j = 0; j < 6; ++j) {
                float4 ha = hv[2*j];
                float4 hb = hv[2*j+1];
                q0 = ffma2(wh2[4*j],     pk2(ha.x, ha.y), q0);
                q1 = ffma2(wh2[4*j + 1], pk2(ha.z, ha.w), q1);
                q2 = ffma2(wh2[4*j + 2], pk2(hb.x, hb.y), q2);
                q3 = ffma2(wh2[4*j + 3], pk2(hb.z, hb.w), q3);
            }
            float4 hc = hv[12];
            q0 = ffma2(wh2[24], pk2(hc.x, hc.y), q0);
            q1 = ffma2(wh2[25], pk2(hc.z, hc.w), q1);
        }
        // gates1 finish + activation + quad shuffle + cell1
        {
            float g1K = fmaf(w7K, err, a1p);
            float v0 = fmaf(tanha(g1K), actK, actA);
            float I = __shfl_sync(0xffffffffu, v0, j0);
            float F = __shfl_sync(0xffffffffu, v0, j0 + 8);
            float G = __shfl_sync(0xffffffffu, v0, j0 + 16);
            float O = __shfl_sync(0xffffffffu, v0, j0 + 24);
            c1 = fmaf(F, c1, I * G);
            float h1v = O * tanha(c1);
            if (k == 0 && writer) sh1[u] = h1v;
        }
        __syncthreads();   // BAR_A: h1(s) ready

        // ================= Phase B =================
        // one pass over sh1 feeds W_ih2@h1 (4 chains) AND W_hh1@h1 (2 chains)
        u64 r0 = pk2(0.0f, 0.0f), r1 = r0, r2 = r0, r3 = r0;
        {
            const float4* hv = (const float4*)sh1;
            #pragma unroll
            for (int j = 0; j < 6; ++j) {
                float4 ha = hv[2*j];
                float4 hb = hv[2*j+1];
                u64 hal = pk2(ha.x, ha.y), hah = pk2(ha.z, ha.w);
                u64 hbl = pk2(hb.x, hb.y), hbh = pk2(hb.z, hb.w);
                r0 = ffma2(wi2[4*j],     hal, r0);
                r1 = ffma2(wi2[4*j + 1], hah, r1);
                r2 = ffma2(wi2[4*j + 2], hbl, r2);
                r3 = ffma2(wi2[4*j + 3], hbh, r3);
                a0 = ffma2(wh1[4*j],     hal, a0);
                a1 = ffma2(wh1[4*j + 1], hah, a1);
                a0 = ffma2(wh1[4*j + 2], hbl, a0);
                a1 = ffma2(wh1[4*j + 3], hbh, a1);
            }
            float4 hc = hv[12];
            u64 hcl = pk2(hc.x, hc.y), hch = pk2(hc.z, hc.w);
            r0 = ffma2(wi2[24], hcl, r0);
            r1 = ffma2(wi2[25], hch, r1);
            a0 = ffma2(wh1[24], hcl, a0);
            a1 = ffma2(wh1[25], hch, a1);
        }
        {
            u64 m = add2(add2(add2(q0, q1), add2(q2, q3)),
                         add2(add2(r0, r1), add2(r2, r3)));
            float2 mf = upk2(m);
            float g2K = mf.x + mf.y;
            float2 af = upk2(add2(a0, a1));
            a1p = af.x + af.y;                                  // K*gates1-partial(s+1)
            float v0 = fmaf(tanha(g2K), actK, actA);
            float I = __shfl_sync(0xffffffffu, v0, j0);
            float F = __shfl_sync(0xffffffffu, v0, j0 + 8);
            float G = __shfl_sync(0xffffffffu, v0, j0 + 16);
            float O = __shfl_sync(0xffffffffu, v0, j0 + 24);
            c2 = fmaf(F, c2, I * G);
            float h2v = O * tanha(c2);
            if (k == 0 && writer) {
                sh2[u] = h2v;
                parr[u] = wout_u * h2v;   // one STS; no shuffle tail
            }
        }
        x7_use = x7_next;          // x7(s-1) -> x7(s) for Phase A(s+1)
        x7_next = xb.w;            // x7(s+1)
        __syncthreads();   // BAR_B: h2(s), parr(s), a1p(s+1) ready
    }

    // epilogue: y(T-1) from final parr
    if (t == 0) {
        float y = bo;
        for (int j = 0; j < HDIM; ++j) y += parr[j];
        out[T - 1] = y;
    }
}

extern "C" void kernel_launch(void* const* d_in, const int* in_sizes, int n_in,
                              void* d_out, int out_size) {
    const int T = in_sizes[0] / INP;
    lstm_r14_kernel<<<1, NTHREADS>>>(
        (const float*)d_in[0],
        (const float*)d_in[1], (const float*)d_in[2],
        (const float*)d_in[3], (const float*)d_in[4],
        (const float*)d_in[5], (const float*)d_in[6],
        (const float*)d_in[7], (const float*)d_in[8],
        (const float*)d_in[9], (const float*)d_in[10],
        (float*)d_out, T);
}

// round 16
// speedup vs baseline: 1.1485x; 1.1485x over previous
#include <cuda_runtime.h>

// 2-layer LSTM (H=50), T=65536 serial steps, one persistent CTA, 256 threads.
// R12 skeleton (shuffle-quad gates, overlapping 8-warp unit coverage, ypart
// y-reduction via shfl butterfly, 2 barriers) + err linearization:
//   g1K = pre + negW*y  where  pre = a1p + w7K*e0,  e0 = 0.9*err + 0.1*x7,
// both computed at the Phase-B tail (off the critical path), so Phase A's
// head is just: load ypart -> y -> 1 fma -> tanh.
// (R15's redux.sync.add.f32 is NOT supported on sm_103 — reverted to the
// 3-level shfl.xor butterfly.)

#define HDIM     50
#define INP      8
#define CHUNK    1024
#define NTHREADS 256

typedef unsigned long long u64;

__device__ __forceinline__ u64 pk2(float lo, float hi) {
    u64 r; asm("mov.b64 %0, {%1,%2};" : "=l"(r) : "f"(lo), "f"(hi)); return r;
}
__device__ __forceinline__ float2 upk2(u64 v) {
    float2 f; asm("mov.b64 {%0,%1}, %2;" : "=f"(f.x), "=f"(f.y) : "l"(v)); return f;
}
__device__ __forceinline__ u64 ffma2(u64 a, u64 b, u64 c) {
    u64 d; asm("fma.rn.f32x2 %0, %1, %2, %3;" : "=l"(d) : "l"(a), "l"(b), "l"(c)); return d;
}
__device__ __forceinline__ u64 add2(u64 a, u64 b) {
    u64 d; asm("add.rn.f32x2 %0, %1, %2;" : "=l"(d) : "l"(a), "l"(b)); return d;
}
__device__ __forceinline__ float tanha(float x) {
    float r; asm("tanh.approx.f32 %0, %1;" : "=f"(r) : "f"(x)); return r;
}

__global__ __launch_bounds__(NTHREADS, 1)
void lstm_r16_kernel(const float* __restrict__ input_seq,
                     const float* __restrict__ W_ih1, const float* __restrict__ W_hh1,
                     const float* __restrict__ b_ih1, const float* __restrict__ b_hh1,
                     const float* __restrict__ W_ih2, const float* __restrict__ W_hh2,
                     const float* __restrict__ b_ih2, const float* __restrict__ b_hh2,
                     const float* __restrict__ W_out, const float* __restrict__ b_out,
                     float* __restrict__ out, int T)
{
    __shared__ __align__(16) float sh1[52];    // h1(s), [50..51]=0
    __shared__ __align__(16) float sh2[52];    // h2(s), [50..51]=0
    __shared__ __align__(16) float ypart[8];   // per-warp wout.h2 partials
    __shared__ __align__(16) float xbuf[(CHUNK + 1) * INP];

    const int t = threadIdx.x;
    const int w = t >> 5;
    const int l = t & 31;
    const int k = l >> 3;                 // gate kind: 0=i 1=f 2=g 3=o
    const int j0 = l & 7;                 // unit-within-warp
    const int u = 6 * w + j0;             // unit 0..49 (overlapping coverage)
    const bool writer = (j0 < 6) || (w == 7);   // unique owner of unit u
    const int row = k * HDIM + u;

    // activation: act(x) = fmaf(tanha(K*x), K, A); K folded into the weights
    const float actK = (k == 2) ? 1.0f : 0.5f;
    const float actA = (k == 2) ? 0.0f : 0.5f;

    // ---- per-thread full-row weights, pre-scaled by actK (f32x2; [25]=pad)
    u64 wx[3], wh1[26], wi2[26], wh2[26];
    float w6K, w7K, bb1K, bb2K;
    {
        const float* r1 = W_ih1 + row * INP;
        wx[0] = pk2(actK * r1[0], actK * r1[1]);
        wx[1] = pk2(actK * r1[2], actK * r1[3]);
        wx[2] = pk2(actK * r1[4], actK * r1[5]);
        w6K = actK * r1[6]; w7K = actK * r1[7];
        const float* r2 = W_hh1 + row * HDIM;
        const float* r3 = W_ih2 + row * HDIM;
        const float* r4 = W_hh2 + row * HDIM;
        #pragma unroll
        for (int j = 0; j < 25; ++j) {
            wh1[j] = pk2(actK * r2[2*j], actK * r2[2*j+1]);
            wi2[j] = pk2(actK * r3[2*j], actK * r3[2*j+1]);
            wh2[j] = pk2(actK * r4[2*j], actK * r4[2*j+1]);
        }
        wh1[25] = 0ULL; wi2[25] = 0ULL; wh2[25] = 0ULL;
        bb1K = actK * (b_ih1[row] + b_hh1[row]);
        bb2K = actK * (b_ih2[row] + b_hh2[row]);
    }
    const float negW = -0.1f * w7K;       // g1K = fmaf(negW, y, pre)
    const float bo = b_out[0];
    const float wout_u = (k == 0 && writer) ? W_out[u] : 0.0f;
    if (t < 52) { sh1[t] = 0.0f; sh2[t] = 0.0f; }
    if (t < 8)  ypart[t] = 0.0f;

    float c1 = 0.0f, c2 = 0.0f, err = 0.0f, a1p = 0.0f;
    float e0 = 0.0f, pre = 0.0f;
    float x7_use = 0.0f, x7_next = 0.0f;
    __syncthreads();

    #pragma unroll 1
    for (int s = 0; s < T; ++s) {
        const int lo = s & (CHUNK - 1);
        if (lo == 0) {
            // old xbuf fully consumed at BAR_B of step s-1
            const float4* src = (const float4*)(input_seq + (size_t)s * INP);
            float4* dst = (float4*)xbuf;
            int n4 = (CHUNK + 1) * 2;
            int rem4 = (T - s) * 2;
            if (rem4 < n4) n4 = rem4;
            for (int i = t; i < n4; i += NTHREADS) dst[i] = src[i];
            __syncthreads();
            if (s == 0) {
                // bootstrap a1p(0) = K*(bb1 + W_ih1 @ x(0)[0..6]); x7_next = x(0)[7]
                float4 xa = *(const float4*)(xbuf);
                float4 xb = *(const float4*)(xbuf + 4);
                u64 a0 = ffma2(wx[0], pk2(xa.x, xa.y), pk2(bb1K, 0.0f));
                u64 a1 = ffma2(wx[1], pk2(xa.z, xa.w), pk2(w6K * xb.z, 0.0f));
                a0 = ffma2(wx[2], pk2(xb.x, xb.y), a0);
                float2 f = upk2(add2(a0, a1));
                a1p = f.x + f.y;
                x7_next = xb.w;
                // s=0: y reads as bo (ypart zeroed); choose e0/pre so that
                // g1K = pre + negW*bo = a1p and err = e0 - 0.1*bo = 0.
                e0 = 0.1f * bo;
                pre = fmaf(-negW, bo, a1p);
            }
        }

        // ================= Phase A =================
        // y(s-1) from per-warp partials — the critical head; issue LDS first
        float y;
        {
            float4 yp0 = *(const float4*)(ypart);
            float4 yp1 = *(const float4*)(ypart + 4);
            y = bo + (((yp0.x + yp0.y) + (yp0.z + yp0.w)) +
                      ((yp1.x + yp1.y) + (yp1.z + yp1.w)));
        }
        // x(s+1) early loads + W_ih1@x FMAs (off-path; carried into Phase B)
        const float* xn = &xbuf[(lo + 1) * INP];
        float4 xa = *(const float4*)(xn);
        float4 xb = *(const float4*)(xn + 4);
        u64 a0 = ffma2(wx[0], pk2(xa.x, xa.y), pk2(bb1K, 0.0f));
        u64 a1 = ffma2(wx[1], pk2(xa.z, xa.w), pk2(w6K * xb.z, 0.0f));
        a0 = ffma2(wx[2], pk2(xb.x, xb.y), a0);

        err = fmaf(-0.1f, y, e0);                     // off the g1K path
        if (t == 0 && s != 0) out[s - 1] = y;

        // W_hh2 @ h2(s-1), 4 ILP chains (carried across BAR_A)
        u64 q0 = pk2(bb2K, 0.0f), q1 = pk2(0.0f, 0.0f), q2 = q1, q3 = q1;
        {
            const float4* hv = (const float4*)sh2;
            #pragma unroll
            for (int j = 0; j < 6; ++j) {
                float4 ha = hv[2*j];
                float4 hb = hv[2*j+1];
                q0 = ffma2(wh2[4*j],     pk2(ha.x, ha.y), q0);
                q1 = ffma2(wh2[4*j + 1], pk2(ha.z, ha.w), q1);
                q2 = ffma2(wh2[4*j + 2], pk2(hb.x, hb.y), q2);
                q3 = ffma2(wh2[4*j + 3], pk2(hb.z, hb.w), q3);
            }
            float4 hc = hv[12];
            q0 = ffma2(wh2[24], pk2(hc.x, hc.y), q0);
            q1 = ffma2(wh2[25], pk2(hc.z, hc.w), q1);
        }
        // gates1 finish + activation + quad shuffle + cell1
        {
            float g1K = fmaf(negW, y, pre);
            float v0 = fmaf(tanha(g1K), actK, actA);
            float I = __shfl_sync(0xffffffffu, v0, j0);
            float F = __shfl_sync(0xffffffffu, v0, j0 + 8);
            float G = __shfl_sync(0xffffffffu, v0, j0 + 16);
            float O = __shfl_sync(0xffffffffu, v0, j0 + 24);
            c1 = fmaf(F, c1, I * G);
            float h1v = O * tanha(c1);
            if (k == 0 && writer) sh1[u] = h1v;
        }
        __syncthreads();   // BAR_A: h1(s) ready

        // ================= Phase B =================
        // one pass over sh1 feeds W_ih2@h1 (4 chains) AND W_hh1@h1 (2 chains)
        u64 r0 = pk2(0.0f, 0.0f), r1 = r0, r2 = r0, r3 = r0;
        {
            const float4* hv = (const float4*)sh1;
            #pragma unroll
            for (int j = 0; j < 6; ++j) {
                float4 ha = hv[2*j];
                float4 hb = hv[2*j+1];
                u64 hal = pk2(ha.x, ha.y), hah = pk2(ha.z, ha.w);
                u64 hbl = pk2(hb.x, hb.y), hbh = pk2(hb.z, hb.w);
                r0 = ffma2(wi2[4*j],     hal, r0);
                r1 = ffma2(wi2[4*j + 1], hah, r1);
                r2 = ffma2(wi2[4*j + 2], hbl, r2);
                r3 = ffma2(wi2[4*j + 3], hbh, r3);
                a0 = ffma2(wh1[4*j],     hal, a0);
                a1 = ffma2(wh1[4*j + 1], hah, a1);
                a0 = ffma2(wh1[4*j + 2], hbl, a0);
                a1 = ffma2(wh1[4*j + 3], hbh, a1);
            }
            float4 hc = hv[12];
            u64 hcl = pk2(hc.x, hc.y), hch = pk2(hc.z, hc.w);
            r0 = ffma2(wi2[24], hcl, r0);
            r1 = ffma2(wi2[25], hch, r1);
            a0 = ffma2(wh1[24], hcl, a0);
            a1 = ffma2(wh1[25], hch, a1);
        }
        {
            u64 m = add2(add2(add2(q0, q1), add2(q2, q3)),
                         add2(add2(r0, r1), add2(r2, r3)));
            float2 mf = upk2(m);
            float g2K = mf.x + mf.y;
            float2 af = upk2(add2(a0, a1));
            a1p = af.x + af.y;                                  // K*gates1-partial(s+1)
            float v0 = fmaf(tanha(g2K), actK, actA);
            float I = __shfl_sync(0xffffffffu, v0, j0);
            float F = __shfl_sync(0xffffffffu, v0, j0 + 8);
            float G = __shfl_sync(0xffffffffu, v0, j0 + 16);
            float O = __shfl_sync(0xffffffffu, v0, j0 + 24);
            c2 = fmaf(F, c2, I * G);
            float h2v = O * tanha(c2);
            // y-partial reduction interleaved with the state store (independent)
            float py = wout_u * h2v;
            if (k == 0 && writer) sh2[u] = h2v;
            py += __shfl_xor_sync(0xffffffffu, py, 1);
            py += __shfl_xor_sync(0xffffffffu, py, 2);
            py += __shfl_xor_sync(0xffffffffu, py, 4);
            if (l == 0) ypart[w] = py;
        }
        // off-path tail: rotate x7 and pre-linearize next step's err path
        x7_use = x7_next;                       // now = x7(s)
        x7_next = xb.w;                         // x7(s+1)
        e0 = fmaf(0.9f, err, 0.1f * x7_use);    // e0(s+1)
        pre = fmaf(w7K, e0, a1p);               // gates1(s+1) pre-combine
        __syncthreads();   // BAR_B: h2(s), ypart(s), a1p(s+1) ready
    }

    // epilogue: y(T-1) from final ypart
    if (t == 0) {
        float y = bo;
        #pragma unroll
        for (int j = 0; j < 8; ++j) y += ypart[j];
        out[T - 1] = y;
    }
}

extern "C" void kernel_launch(void* const* d_in, const int* in_sizes, int n_in,
                              void* d_out, int out_size) {
    const int T = in_sizes[0] / INP;
    lstm_r16_kernel<<<1, NTHREADS>>>(
        (const float*)d_in[0],
        (const float*)d_in[1], (const float*)d_in[2],
        (const float*)d_in[3], (const float*)d_in[4],
        (const float*)d_in[5], (const float*)d_in[6],
        (const float*)d_in[7], (const float*)d_in[8],
        (const float*)d_in[9], (const float*)d_in[10],
        (float*)d_out, T);
}

// round 17
// speedup vs baseline: 1.1902x; 1.0363x over previous
#include <cuda_runtime.h>

// 2-layer LSTM (H=50), T=65536 serial steps. Two kernels:
//  1) xdot_kernel (full chip): g_xdot[s][row] = K*(bb1 + W_ih1[row,0:7]@x[s,0:7])
//     — the input-dependent part of layer-1 gates, independent of recurrence.
//  2) lstm persistent kernel (R16 skeleton: shuffle-quad gates, overlapping
//     8-warp unit coverage, ypart y-reduction, err linearization, 2 barriers)
//     with ALL per-step input processing replaced by two prefetched LDGs
//     (g_xdot and x7, issued 3 steps ahead). xbuf/chunk staging removed.

#define HDIM     50
#define INP      8
#define NTHREADS 256
#define TMAX     65536

typedef unsigned long long u64;

__device__ float g_xdot[TMAX * 200];   // 52.4MB scratch (device global)

__device__ __forceinline__ u64 pk2(float lo, float hi) {
    u64 r; asm("mov.b64 %0, {%1,%2};" : "=l"(r) : "f"(lo), "f"(hi)); return r;
}
__device__ __forceinline__ float2 upk2(u64 v) {
    float2 f; asm("mov.b64 {%0,%1}, %2;" : "=f"(f.x), "=f"(f.y) : "l"(v)); return f;
}
__device__ __forceinline__ u64 ffma2(u64 a, u64 b, u64 c) {
    u64 d; asm("fma.rn.f32x2 %0, %1, %2, %3;" : "=l"(d) : "l"(a), "l"(b), "l"(c)); return d;
}
__device__ __forceinline__ u64 add2(u64 a, u64 b) {
    u64 d; asm("add.rn.f32x2 %0, %1, %2;" : "=l"(d) : "l"(a), "l"(b)); return d;
}
__device__ __forceinline__ float tanha(float x) {
    float r; asm("tanh.approx.f32 %0, %1;" : "=f"(r) : "f"(x)); return r;
}

// ---------------- kernel 1: precompute x-dots ----------------
__global__ void xdot_kernel(const float* __restrict__ input_seq,
                            const float* __restrict__ W_ih1,
                            const float* __restrict__ b_ih1,
                            const float* __restrict__ b_hh1, int T)
{
    __shared__ float sW[200 * 9];   // stride 9 to dodge bank conflicts
    __shared__ float sB[200];
    __shared__ float sx[128 * 8];

    const int tid = threadIdx.x;    // 256
    for (int i = tid; i < 200 * 8; i += 256) {
        int r = i >> 3, c = i & 7;
        sW[r * 9 + c] = W_ih1[i];
    }
    for (int i = tid; i < 200; i += 256) {
        float K = (i >= 100 && i < 150) ? 1.0f : 0.5f;
        sB[i] = K * (b_ih1[i] + b_hh1[i]);
    }
    const int s0 = blockIdx.x * 128;
    for (int i = tid; i < 128 * 8; i += 256) {
        int gi = s0 * 8 + i;
        sx[i] = (gi < T * INP) ? input_seq[gi] : 0.0f;
    }
    __syncthreads();

    for (int idx = tid; idx < 128 * 200; idx += 256) {
        int sl = idx / 200;
        int row = idx - sl * 200;
        int s = s0 + sl;
        if (s >= T) continue;
        float K = (row >= 100 && row < 150) ? 1.0f : 0.5f;
        const float* wr = &sW[row * 9];
        const float* xr = &sx[sl * 8];
        float d = 0.0f;
        #pragma unroll
        for (int j = 0; j < 7; ++j) d = fmaf(wr[j], xr[j], d);
        g_xdot[s * 200 + row] = fmaf(K, d, sB[row]);
    }
}

// ---------------- kernel 2: persistent recurrence ----------------
__global__ __launch_bounds__(NTHREADS, 1)
void lstm_r17_kernel(const float* __restrict__ input_seq,
                     const float* __restrict__ W_ih1, const float* __restrict__ W_hh1,
                     const float* __restrict__ b_ih1, const float* __restrict__ b_hh1,
                     const float* __restrict__ W_ih2, const float* __restrict__ W_hh2,
                     const float* __restrict__ b_ih2, const float* __restrict__ b_hh2,
                     const float* __restrict__ W_out, const float* __restrict__ b_out,
                     float* __restrict__ out, int T)
{
    __shared__ __align__(16) float sh1[52];    // h1(s), [50..51]=0
    __shared__ __align__(16) float sh2[52];    // h2(s), [50..51]=0
    __shared__ __align__(16) float ypart[8];   // per-warp wout.h2 partials

    const int t = threadIdx.x;
    const int w = t >> 5;
    const int l = t & 31;
    const int k = l >> 3;                 // gate kind: 0=i 1=f 2=g 3=o
    const int j0 = l & 7;                 // unit-within-warp
    const int u = 6 * w + j0;             // unit 0..49 (overlapping coverage)
    const bool writer = (j0 < 6) || (w == 7);   // unique owner of unit u
    const int row = k * HDIM + u;

    const float actK = (k == 2) ? 1.0f : 0.5f;
    const float actA = (k == 2) ? 0.0f : 0.5f;

    // ---- per-thread recurrent weights, pre-scaled by actK (f32x2; [25]=pad)
    u64 wh1[26], wi2[26], wh2[26];
    float w7K, bb2K;
    {
        const float* r2 = W_hh1 + row * HDIM;
        const float* r3 = W_ih2 + row * HDIM;
        const float* r4 = W_hh2 + row * HDIM;
        #pragma unroll
        for (int j = 0; j < 25; ++j) {
            wh1[j] = pk2(actK * r2[2*j], actK * r2[2*j+1]);
            wi2[j] = pk2(actK * r3[2*j], actK * r3[2*j+1]);
            wh2[j] = pk2(actK * r4[2*j], actK * r4[2*j+1]);
        }
        wh1[25] = 0ULL; wi2[25] = 0ULL; wh2[25] = 0ULL;
        w7K = actK * W_ih1[row * INP + 7];
        bb2K = actK * (b_ih2[row] + b_hh2[row]);
    }
    const float negW = -0.1f * w7K;       // g1K = fmaf(negW, y, pre)
    const float bo = b_out[0];
    const float wout_u = (k == 0 && writer) ? W_out[u] : 0.0f;
    if (t < 52) { sh1[t] = 0.0f; sh2[t] = 0.0f; }
    if (t < 8)  ypart[t] = 0.0f;

    // ---- bootstrap prefetch pipeline (xd, x7), clamped for tiny T
    const int i1 = (T > 1) ? 1 : 0;
    const int i2 = (T > 2) ? 2 : 0;
    float xd_use = g_xdot[i1 * 200 + row];         // xd(1): Phase B(0) seed
    float xd_a   = g_xdot[i2 * 200 + row];         // xd(2)
    float x7_0 = input_seq[7];                     // x7(0)
    float x7_1 = input_seq[i1 * INP + 7];
    float x7_2 = input_seq[i2 * INP + 7];
    float xd0 = g_xdot[row];                       // xd(0)

    float c1 = 0.0f, c2 = 0.0f, err = 0.0f;
    // s=0: y reads as bo (ypart zeroed); e0/pre chosen so g1K(0)=xd(0), err(0)=0
    float e0 = 0.1f * bo;
    float pre = fmaf(-negW, bo, xd0);
    __syncthreads();

    #pragma unroll 1
    for (int s = 0; s < T; ++s) {
        // ================= Phase A =================
        // prefetch step s+3 (xd row value + x7), consumed at tail of B(s+2)
        int sp = s + 3; sp = (sp < T) ? sp : (T - 1);
        float xd_new = g_xdot[sp * 200 + row];
        float x7_new = input_seq[sp * INP + 7];

        // y(s-1) from per-warp partials — critical head
        float y;
        {
            float4 yp0 = *(const float4*)(ypart);
            float4 yp1 = *(const float4*)(ypart + 4);
            y = bo + (((yp0.x + yp0.y) + (yp0.z + yp0.w)) +
                      ((yp1.x + yp1.y) + (yp1.z + yp1.w)));
        }
        err = fmaf(-0.1f, y, e0);                     // off the g1K path
        if (t == 0 && s != 0) out[s - 1] = y;

        // W_hh2 @ h2(s-1), 4 ILP chains (carried across BAR_A)
        u64 q0 = pk2(bb2K, 0.0f), q1 = pk2(0.0f, 0.0f), q2 = q1, q3 = q1;
        {
            const float4* hv = (const float4*)sh2;
            #pragma unroll
            for (int j = 0; j < 6; ++j) {
                float4 ha = hv[2*j];
                float4 hb = hv[2*j+1];
                q0 = ffma2(wh2[4*j],     pk2(ha.x, ha.y), q0);
                q1 = ffma2(wh2[4*j + 1], pk2(ha.z, ha.w), q1);
                q2 = ffma2(wh2[4*j + 2], pk2(hb.x, hb.y), q2);
                q3 = ffma2(wh2[4*j + 3], pk2(hb.z, hb.w), q3);
            }
            float4 hc = hv[12];
            q0 = ffma2(wh2[24], pk2(hc.x, hc.y), q0);
            q1 = ffma2(wh2[25], pk2(hc.z, hc.w), q1);
        }
        // gates1 finish + activation + quad shuffle + cell1
        {
            float g1K = fmaf(negW, y, pre);
            float v0 = fmaf(tanha(g1K), actK, actA);
            float I = __shfl_sync(0xffffffffu, v0, j0);
            float F = __shfl_sync(0xffffffffu, v0, j0 + 8);
            float G = __shfl_sync(0xffffffffu, v0, j0 + 16);
            float O = __shfl_sync(0xffffffffu, v0, j0 + 24);
            c1 = fmaf(F, c1, I * G);
            float h1v = O * tanha(c1);
            if (k == 0 && writer) sh1[u] = h1v;
        }
        __syncthreads();   // BAR_A: h1(s) ready

        // ================= Phase B =================
        // one pass over sh1 feeds W_ih2@h1 (4 chains) AND W_hh1@h1 (2 chains,
        // seeded with the precomputed xd(s+1))
        u64 a0 = pk2(xd_use, 0.0f), a1 = pk2(0.0f, 0.0f);
        u64 r0 = pk2(0.0f, 0.0f), r1 = r0, r2 = r0, r3 = r0;
        {
            const float4* hv = (const float4*)sh1;
            #pragma unroll
            for (int j = 0; j < 6; ++j) {
                float4 ha = hv[2*j];
                float4 hb = hv[2*j+1];
                u64 hal = pk2(ha.x, ha.y), hah = pk2(ha.z, ha.w);
                u64 hbl = pk2(hb.x, hb.y), hbh = pk2(hb.z, hb.w);
                r0 = ffma2(wi2[4*j],     hal, r0);
                r1 = ffma2(wi2[4*j + 1], hah, r1);
                r2 = ffma2(wi2[4*j + 2], hbl, r2);
                r3 = ffma2(wi2[4*j + 3], hbh, r3);
                a0 = ffma2(wh1[4*j],     hal, a0);
                a1 = ffma2(wh1[4*j + 1], hah, a1);
                a0 = ffma2(wh1[4*j + 2], hbl, a0);
                a1 = ffma2(wh1[4*j + 3], hbh, a1);
            }
            float4 hc = hv[12];
            u64 hcl = pk2(hc.x, hc.y), hch = pk2(hc.z, hc.w);
            r0 = ffma2(wi2[24], hcl, r0);
            r1 = ffma2(wi2[25], hch, r1);
            a0 = ffma2(wh1[24], hcl, a0);
            a1 = ffma2(wh1[25], hch, a1);
        }
        float a1p;
        {
            u64 m = add2(add2(add2(q0, q1), add2(q2, q3)),
                         add2(add2(r0, r1), add2(r2, r3)));
            float2 mf = upk2(m);
            float g2K = mf.x + mf.y;
            float2 af = upk2(add2(a0, a1));
            a1p = af.x + af.y;                        // xd(s+1) + K*Wh1@h1(s)
            float v0 = fmaf(tanha(g2K), actK, actA);
            float I = __shfl_sync(0xffffffffu, v0, j0);
            float F = __shfl_sync(0xffffffffu, v0, j0 + 8);
            float G = __shfl_sync(0xffffffffu, v0, j0 + 16);
            float O = __shfl_sync(0xffffffffu, v0, j0 + 24);
            c2 = fmaf(F, c2, I * G);
            float h2v = O * tanha(c2);
            float py = wout_u * h2v;
            if (k == 0 && writer) sh2[u] = h2v;
            py += __shfl_xor_sync(0xffffffffu, py, 1);
            py += __shfl_xor_sync(0xffffffffu, py, 2);
            py += __shfl_xor_sync(0xffffffffu, py, 4);
            if (l == 0) ypart[w] = py;
        }
        // off-path tail: advance err linearization + prefetch pipelines
        e0 = fmaf(0.9f, err, 0.1f * x7_0);    // e0(s+1), uses x7(s)
        pre = fmaf(w7K, e0, a1p);             // gates1(s+1) pre-combine
        x7_0 = x7_1; x7_1 = x7_2; x7_2 = x7_new;
        xd_use = xd_a; xd_a = xd_new;
        __syncthreads();   // BAR_B: h2(s), ypart(s), pre(s+1) ready
    }

    // epilogue: y(T-1) from final ypart
    if (t == 0) {
        float y = bo;
        #pragma unroll
        for (int j = 0; j < 8; ++j) y += ypart[j];
        out[T - 1] = y;
    }
}

extern "C" void kernel_launch(void* const* d_in, const int* in_sizes, int n_in,
                              void* d_out, int out_size) {
    const int T = in_sizes[0] / INP;
    const float* input_seq = (const float*)d_in[0];
    xdot_kernel<<<(T + 127) / 128, 256>>>(input_seq,
                                          (const float*)d_in[1],
                                          (const float*)d_in[3],
                                          (const float*)d_in[4], T);
    lstm_r17_kernel<<<1, NTHREADS>>>(
        input_seq,
        (const float*)d_in[1], (const float*)d_in[2],
        (const float*)d_in[3], (const float*)d_in[4],
        (const float*)d_in[5], (const float*)d_in[6],
        (const float*)d_in[7], (const float*)d_in[8],
        (const float*)d_in[9], (const float*)d_in[10],
        (float*)d_out, T);
}